// round 3
// baseline (speedup 1.0000x reference)
#include <cuda_runtime.h>
#include <math.h>

// Problem constants
#define BB 4
#define LL 4092
#define HH 8
#define DH 64
#define DM 512
#define WS 12
#define STEP 6
#define NW 681
#define LNEPS 1e-5f
#define WB 8                            // windows per block
#define NBLK_BH ((NW + WB - 1) / WB)    // 86
#define MAXROWS 54                      // WB*6 + 6

// scratch: per-window attention outputs only (projections stay in smem now)
__device__ float g_ow[BB*HH*NW*WS*DH];

// =============================================================================
// Fused kernel: per-block -> project 54-row span (3 matrices), then windowed
// attention for WB=8 windows. 256 threads.
// smem (floats):  Xs[54][68] (raw X, later reused as P), Wt[64][68],
//                 Qs/Ks/Vs[54][68]   => 19040 floats = 76160 B -> 3 CTAs/SM
// =============================================================================
__global__ __launch_bounds__(256, 3) void fused_kernel(
    const float* __restrict__ q, const float* __restrict__ k, const float* __restrict__ v,
    const float* __restrict__ Wq, const float* __restrict__ Wk, const float* __restrict__ Wv,
    float* __restrict__ attn_out)
{
    extern __shared__ float sm[];
    float* Xs = sm;                    // 54*68 = 3672  (reused as P later)
    float* Wt = Xs + MAXROWS*68;       // 64*68 = 4352
    float* Qs = Wt + 64*68;            // 54*68
    float* Ks = Qs + MAXROWS*68;
    float* Vs = Ks + MAXROWS*68;
    float* P  = Xs;                    // overlay: P[WB*144=1152] <= 3672

    const int tid = threadIdx.x;
    const int blk = blockIdx.x;
    const int bh = blk / NBLK_BH;      // b*HH + h
    const int ng = blk - bh * NBLK_BH;
    const int b  = bh >> 3;
    const int h  = bh & 7;
    const int n0 = ng * WB;
    const int nwin = (NW - n0 < WB) ? (NW - n0) : WB;
    const int rows = nwin*6 + 6;
    const int t0 = n0 * STEP;

    // proj-compute thread mapping: rt = tid/8 (row pair), et = tid%8 (8 cols)
    const int rt = tid >> 3;           // 0..31, active < 27
    const int et = tid & 7;

    const float* Xsrc[3] = {q, k, v};
    const float* Wsrc[3] = {Wq, Wk, Wv};
    float* Dst[3] = {Qs, Ks, Vs};

    for (int m = 0; m < 3; m++) {
        // ---- load W transposed: Wt[d][e] = W[e][d]
        {
            const float* W = Wsrc[m];
            for (int idx = tid; idx < 1024; idx += 256) {
                int e = idx >> 4, d4 = idx & 15;
                float4 wv = reinterpret_cast<const float4*>(W)[idx];
                Wt[(d4*4+0)*68 + e] = wv.x;
                Wt[(d4*4+1)*68 + e] = wv.y;
                Wt[(d4*4+2)*68 + e] = wv.z;
                Wt[(d4*4+3)*68 + e] = wv.w;
            }
        }
        // ---- load raw X rows for this span: X[b, t0+r, h, :]
        {
            const float* X = Xsrc[m];
            for (int idx = tid; idx < rows*16; idx += 256) {
                int r = idx >> 4, c4 = idx & 15;
                const float4* src = reinterpret_cast<const float4*>(
                    X + (((size_t)b*LL + (t0 + r))*HH + h)*64) + c4;
                *reinterpret_cast<float4*>(&Xs[r*68 + c4*4]) = *src;
            }
            // zero-fill unused rows (last group) so dummy compute is finite
            for (int idx = rows*16 + tid; idx < MAXROWS*16; idx += 256) {
                int r = idx >> 4, c4 = idx & 15;
                *reinterpret_cast<float4*>(&Xs[r*68 + c4*4]) =
                    make_float4(0.f, 0.f, 0.f, 0.f);
            }
        }
        __syncthreads();

        // ---- compute: out[r][e] = sum_d Xs[r][d] * Wt[d][e]
        if (rt < 27) {
            int r0 = rt*2;
            float acc0[8], acc1[8];
            #pragma unroll
            for (int j = 0; j < 8; j++) { acc0[j] = 0.f; acc1[j] = 0.f; }
            #pragma unroll 8
            for (int d = 0; d < 64; d++) {
                float x0 = Xs[r0*68 + d];
                float x1 = Xs[(r0+1)*68 + d];
                float4 wa = *reinterpret_cast<const float4*>(&Wt[d*68 + et*8]);
                float4 wb = *reinterpret_cast<const float4*>(&Wt[d*68 + et*8 + 4]);
                float wv[8] = {wa.x, wa.y, wa.z, wa.w, wb.x, wb.y, wb.z, wb.w};
                #pragma unroll
                for (int j = 0; j < 8; j++) {
                    acc0[j] = fmaf(x0, wv[j], acc0[j]);
                    acc1[j] = fmaf(x1, wv[j], acc1[j]);
                }
            }
            float* D = Dst[m];
            *reinterpret_cast<float4*>(&D[r0*68 + et*8])     = make_float4(acc0[0],acc0[1],acc0[2],acc0[3]);
            *reinterpret_cast<float4*>(&D[r0*68 + et*8 + 4]) = make_float4(acc0[4],acc0[5],acc0[6],acc0[7]);
            *reinterpret_cast<float4*>(&D[(r0+1)*68 + et*8])     = make_float4(acc1[0],acc1[1],acc1[2],acc1[3]);
            *reinterpret_cast<float4*>(&D[(r0+1)*68 + et*8 + 4]) = make_float4(acc1[4],acc1[5],acc1[6],acc1[7]);
        }
        __syncthreads();   // before Xs/Wt reload next matrix (and before P overlay)
    }

    // ---- scores (P overlays Xs; safe after last sync)
    for (int o = tid; o < nwin*144; o += 256) {
        int w = o / 144;
        int r = o - w*144;
        int qi = r / 12, ki = r - qi*12;
        const float* qr = &Qs[(w*6 + qi)*68];
        const float* kr = &Ks[(w*6 + ki)*68];
        float s = 0.f;
        #pragma unroll
        for (int d = 0; d < 64; d += 4) {
            float4 a = *reinterpret_cast<const float4*>(&qr[d]);
            float4 bb2 = *reinterpret_cast<const float4*>(&kr[d]);
            s = fmaf(a.x, bb2.x, s); s = fmaf(a.y, bb2.y, s);
            s = fmaf(a.z, bb2.z, s); s = fmaf(a.w, bb2.w, s);
        }
        P[o] = s * 0.125f;
    }
    __syncthreads();

    // ---- softmax rows
    for (int t = tid; t < nwin*12; t += 256) {
        int w = t / 12, qi = t - w*12;
        float* row = &P[w*144 + qi*12];
        float mx = row[0];
        #pragma unroll
        for (int k2 = 1; k2 < 12; k2++) mx = fmaxf(mx, row[k2]);
        float sum = 0.f;
        float e[12];
        #pragma unroll
        for (int k2 = 0; k2 < 12; k2++) { e[k2] = __expf(row[k2] - mx); sum += e[k2]; }
        float inv = 1.f / sum;
        #pragma unroll
        for (int k2 = 0; k2 < 12; k2++) row[k2] = e[k2] * inv;
    }
    __syncthreads();

    // ---- write attention probabilities
    if (attn_out) {
        float* dst = attn_out + ((size_t)bh*NW + n0)*144;
        for (int o = tid; o < nwin*144; o += 256) dst[o] = P[o];
    }

    // ---- P @ V -> global ow
    float* owp = &g_ow[((size_t)bh*NW + n0) * (WS*DH)];
    for (int o = tid; o < nwin*WS*DH; o += 256) {
        int w = o / (WS*DH);
        int r = o - w*(WS*DH);
        int qi = r >> 6, e = r & 63;
        const float* prow = &P[w*144 + qi*12];
        const float* vb = &Vs[(w*6)*68 + e];
        float s = 0.f;
        #pragma unroll
        for (int k2 = 0; k2 < 12; k2++)
            s = fmaf(prow[k2], vb[k2*68], s);
        owp[o] = s;
    }
}

// =============================================================================
// Combine: overlap-add average + residual + LayerNorm
// =============================================================================
__global__ __launch_bounds__(128) void combine_kernel(
    const float* __restrict__ queries, const float* __restrict__ gamma,
    const float* __restrict__ beta, float* __restrict__ z)
{
    __shared__ float red[8];

    const int tid = threadIdx.x;
    const int tok = blockIdx.x;
    const int b = tok / LL;
    const int t = tok - b*LL;
    const int c0 = tid * 4;
    const int h = c0 >> 6;
    const int e = c0 & 63;

    const int n1 = t / 6, w1 = t - n1*6;
    const int n0 = n1 - 1, w0 = w1 + 6;

    float4 acc = make_float4(0.f, 0.f, 0.f, 0.f);
    float cnt = 0.f;
    if (n1 < NW) {
        const float* p = &g_ow[(((size_t)(b*HH + h)*NW + n1)*WS + w1)*64 + e];
        float4 v = *reinterpret_cast<const float4*>(p);
        acc.x += v.x; acc.y += v.y; acc.z += v.z; acc.w += v.w; cnt += 1.f;
    }
    if (n0 >= 0) {
        const float* p = &g_ow[(((size_t)(b*HH + h)*NW + n0)*WS + w0)*64 + e];
        float4 v = *reinterpret_cast<const float4*>(p);
        acc.x += v.x; acc.y += v.y; acc.z += v.z; acc.w += v.w; cnt += 1.f;
    }
    float inv = 1.f / cnt;
    float4 resid = *reinterpret_cast<const float4*>(&queries[(size_t)tok*DM + c0]);
    float4 x;
    x.x = acc.x*inv + resid.x; x.y = acc.y*inv + resid.y;
    x.z = acc.z*inv + resid.z; x.w = acc.w*inv + resid.w;

    float s  = x.x + x.y + x.z + x.w;
    float ss = x.x*x.x + x.y*x.y + x.z*x.z + x.w*x.w;
    #pragma unroll
    for (int off = 16; off > 0; off >>= 1) {
        s  += __shfl_down_sync(0xFFFFFFFFu, s, off);
        ss += __shfl_down_sync(0xFFFFFFFFu, ss, off);
    }
    int wid = tid >> 5, lane = tid & 31;
    if (lane == 0) { red[wid] = s; red[4 + wid] = ss; }
    __syncthreads();
    float ts  = red[0] + red[1] + red[2] + red[3];
    float tss = red[4] + red[5] + red[6] + red[7];
    float mean = ts * (1.f / DM);
    float var  = tss * (1.f / DM) - mean*mean;
    float rstd = rsqrtf(var + LNEPS);

    float4 g = *reinterpret_cast<const float4*>(&gamma[c0]);
    float4 bta = *reinterpret_cast<const float4*>(&beta[c0]);
    float4 o;
    o.x = (x.x - mean)*rstd*g.x + bta.x;
    o.y = (x.y - mean)*rstd*g.y + bta.y;
    o.z = (x.z - mean)*rstd*g.z + bta.z;
    o.w = (x.w - mean)*rstd*g.w + bta.w;
    *reinterpret_cast<float4*>(&z[(size_t)tok*DM + c0]) = o;
}

// =============================================================================
extern "C" void kernel_launch(void* const* d_in, const int* in_sizes, int n_in,
                              void* d_out, int out_size) {
    const float* queries = (const float*)d_in[0];
    const float* keys    = (const float*)d_in[1];
    const float* values  = (const float*)d_in[2];
    const float* Wq      = (const float*)d_in[3];
    const float* Wk      = (const float*)d_in[4];
    const float* Wv      = (const float*)d_in[5];
    const float* gamma   = (const float*)d_in[6];
    const float* beta    = (const float*)d_in[7];

    float* z = (float*)d_out;
    const long Z = (long)BB * LL * DM;
    const long A = (long)BB * HH * NW * WS * WS;
    float* attn_out = nullptr;
    if ((long)out_size >= Z + A) attn_out = z + Z;

    const int fused_smem = (MAXROWS*68 + 64*68 + 3*MAXROWS*68) * 4;   // 76160
    static bool attr_set = false;
    if (!attr_set) {
        cudaFuncSetAttribute(fused_kernel, cudaFuncAttributeMaxDynamicSharedMemorySize, fused_smem);
        attr_set = true;
    }

    fused_kernel<<<BB*HH*NBLK_BH, 256, fused_smem>>>(
        queries, keys, values, Wq, Wk, Wv, attn_out);
    combine_kernel<<<BB*LL, 128>>>(queries, gamma, beta, z);
}

// round 4
// speedup vs baseline: 1.6566x; 1.6566x over previous
#include <cuda_runtime.h>
#include <math.h>

// Problem constants
#define BB 4
#define LL 4092
#define HH 8
#define DH 64
#define DM 512
#define WS 12
#define STEP 6
#define NW 681
#define MROWS (BB*LL*HH)   // 130944
#define LNEPS 1e-5f
#define WB 8
#define NBLK_BH ((NW + WB - 1) / WB)   // 86

// ---------------- scratch -----------------
__device__ float g_Qp[BB*HH*LL*DH];
__device__ float g_Kp[BB*HH*LL*DH];
__device__ float g_Vp[BB*HH*LL*DH];
__device__ float g_ow[BB*HH*NW*WS*DH];

// ---------------- packed f32x2 helpers ----------------
__device__ __forceinline__ unsigned long long ffma2(
    unsigned long long a, unsigned long long b, unsigned long long c) {
    unsigned long long d;
    asm("fma.rn.f32x2 %0, %1, %2, %3;" : "=l"(d) : "l"(a), "l"(b), "l"(c));
    return d;
}
__device__ __forceinline__ unsigned long long pack2(float x, float y) {
    unsigned long long d;
    asm("mov.b64 %0, {%1, %2};" : "=l"(d)
        : "r"(__float_as_uint(x)), "r"(__float_as_uint(y)));
    return d;
}
__device__ __forceinline__ void unpack2(unsigned long long p, float& x, float& y) {
    unsigned int lo, hi;
    asm("mov.b64 {%0, %1}, %2;" : "=r"(lo), "=r"(hi) : "l"(p));
    x = __uint_as_float(lo); y = __uint_as_float(hi);
}

// =============================================================================
// Kernel 1: projections. grid = (1023, 3): y selects matrix. 128 threads,
// 128 rows x 64 cols per block, 8x8 per-thread tile, packed FFMA2 inner loop.
//   Xt[64][136] (transposed X), Wt[64][68] (transposed W). smem = 52224 B.
// =============================================================================
__global__ __launch_bounds__(128) void proj_kernel(
    const float* __restrict__ q, const float* __restrict__ k, const float* __restrict__ v,
    const float* __restrict__ Wq, const float* __restrict__ Wk, const float* __restrict__ Wv)
{
    extern __shared__ float sm[];
    float* Xt = sm;                 // 64*136
    float* Wt = sm + 64*136;        // 64*68

    const int tid = threadIdx.x;
    const int lane = tid & 31;
    const int seg  = tid >> 5;
    const int rt = tid >> 3;        // 0..15
    const int ct = tid & 7;         // 0..7
    const int r0 = blockIdx.x * 128;
    const int m  = blockIdx.y;

    const float* X = (m == 0) ? q : (m == 1) ? k : v;
    const float* W = (m == 0) ? Wq : (m == 1) ? Wk : Wv;
    float* Out = (m == 0) ? g_Qp : (m == 1) ? g_Kp : g_Vp;

    // ---- load W transposed
    for (int idx = tid; idx < 1024; idx += 128) {
        int e = idx & 63, d4 = idx >> 6;
        float4 wv = reinterpret_cast<const float4*>(W)[e*16 + d4];
        Wt[(d4*4+0)*68 + e] = wv.x;
        Wt[(d4*4+1)*68 + e] = wv.y;
        Wt[(d4*4+2)*68 + e] = wv.z;
        Wt[(d4*4+3)*68 + e] = wv.w;
    }
    // ---- load X transposed (32 rows per iter, coalesced LDG.128)
    #pragma unroll
    for (int it = 0; it < 4; it++) {
        int row = lane + 32*it;
        const float4* src = reinterpret_cast<const float4*>(
            X + (size_t)(r0 + row)*64 + seg*16);
        float4 a = src[0], b = src[1], c = src[2], d = src[3];
        int db = seg*16;
        Xt[(db+ 0)*136 + row] = a.x; Xt[(db+ 1)*136 + row] = a.y;
        Xt[(db+ 2)*136 + row] = a.z; Xt[(db+ 3)*136 + row] = a.w;
        Xt[(db+ 4)*136 + row] = b.x; Xt[(db+ 5)*136 + row] = b.y;
        Xt[(db+ 6)*136 + row] = b.z; Xt[(db+ 7)*136 + row] = b.w;
        Xt[(db+ 8)*136 + row] = c.x; Xt[(db+ 9)*136 + row] = c.y;
        Xt[(db+10)*136 + row] = c.z; Xt[(db+11)*136 + row] = c.w;
        Xt[(db+12)*136 + row] = d.x; Xt[(db+13)*136 + row] = d.y;
        Xt[(db+14)*136 + row] = d.z; Xt[(db+15)*136 + row] = d.w;
    }
    __syncthreads();

    // ---- compute 8x8 tile: rows packed in pairs, cols broadcast
    unsigned long long acc[4][8];
    #pragma unroll
    for (int ip = 0; ip < 4; ip++)
        #pragma unroll
        for (int j = 0; j < 8; j++) acc[ip][j] = 0ULL;

    #pragma unroll 4
    for (int d = 0; d < 64; d++) {
        float4 xa = *reinterpret_cast<const float4*>(&Xt[d*136 + rt*8]);
        float4 xb = *reinterpret_cast<const float4*>(&Xt[d*136 + rt*8 + 4]);
        float4 wa = *reinterpret_cast<const float4*>(&Wt[d*68 + ct*8]);
        float4 wb = *reinterpret_cast<const float4*>(&Wt[d*68 + ct*8 + 4]);
        unsigned long long xp[4] = {
            pack2(xa.x, xa.y), pack2(xa.z, xa.w),
            pack2(xb.x, xb.y), pack2(xb.z, xb.w)};
        float wv[8] = {wa.x, wa.y, wa.z, wa.w, wb.x, wb.y, wb.z, wb.w};
        unsigned long long wp[8];
        #pragma unroll
        for (int j = 0; j < 8; j++) wp[j] = pack2(wv[j], wv[j]);
        #pragma unroll
        for (int ip = 0; ip < 4; ip++)
            #pragma unroll
            for (int j = 0; j < 8; j++)
                acc[ip][j] = ffma2(xp[ip], wp[j], acc[ip][j]);
    }

    // ---- store to [B,H,L,64]
    #pragma unroll
    for (int ip = 0; ip < 4; ip++) {
        float lo[8], hi[8];
        #pragma unroll
        for (int j = 0; j < 8; j++) unpack2(acc[ip][j], lo[j], hi[j]);
        #pragma unroll
        for (int half = 0; half < 2; half++) {
            const float* val = half ? hi : lo;
            int r = r0 + rt*8 + ip*2 + half;
            int b = r / (LL*HH);
            int rem = r - b*(LL*HH);
            int l = rem >> 3;
            int h = rem & 7;
            size_t orow = ((size_t)(b*HH + h)*LL + l)*64;
            *reinterpret_cast<float4*>(&Out[orow + ct*8]) =
                make_float4(val[0], val[1], val[2], val[3]);
            *reinterpret_cast<float4*>(&Out[orow + ct*8 + 4]) =
                make_float4(val[4], val[5], val[6], val[7]);
        }
    }
}

// =============================================================================
// Kernel 2: attention, WB windows per block, 256 threads, packed math.
// =============================================================================
__global__ __launch_bounds__(256) void attn_kernel(float* __restrict__ attn_out)
{
    extern __shared__ float sm[];
    float* Qs = sm;                 // 54*68
    float* Ks = Qs + 54*68;
    float* Vs = Ks + 54*68;
    float* P  = Vs + 54*68;         // WB*144

    const int tid = threadIdx.x;
    const int blk = blockIdx.x;
    const int bh = blk / NBLK_BH;
    const int ng = blk - bh * NBLK_BH;
    const int n0 = ng * WB;
    const int nwin = (NW - n0 < WB) ? (NW - n0) : WB;
    const int rows = nwin*6 + 6;

    const size_t base = ((size_t)bh * LL + n0*STEP) * 64;

    // ---- load Q/K/V spans
    {
        const float* srcs[3] = {g_Qp + base, g_Kp + base, g_Vp + base};
        float* dsts[3] = {Qs, Ks, Vs};
        int nf4 = rows * 16;
        #pragma unroll
        for (int m = 0; m < 3; m++) {
            const float4* src = reinterpret_cast<const float4*>(srcs[m]);
            float* dst = dsts[m];
            for (int idx = tid; idx < nf4; idx += 256) {
                int row = idx >> 4, c4 = idx & 15;
                float4 val = src[idx];
                *reinterpret_cast<float4*>(&dst[row*68 + c4*4]) = val;
            }
        }
    }
    __syncthreads();

    // ---- scores (packed dot products)
    for (int o = tid; o < nwin*144; o += 256) {
        int w = o / 144;
        int r = o - w*144;
        int qi = r / 12, ki = r - qi*12;
        const float* qr = &Qs[(w*6 + qi)*68];
        const float* kr = &Ks[(w*6 + ki)*68];
        unsigned long long s01 = 0ULL, s23 = 0ULL;
        #pragma unroll
        for (int d = 0; d < 64; d += 4) {
            float4 a = *reinterpret_cast<const float4*>(&qr[d]);
            float4 b = *reinterpret_cast<const float4*>(&kr[d]);
            s01 = ffma2(pack2(a.x, a.y), pack2(b.x, b.y), s01);
            s23 = ffma2(pack2(a.z, a.w), pack2(b.z, b.w), s23);
        }
        float x0, x1, x2, x3;
        unpack2(s01, x0, x1); unpack2(s23, x2, x3);
        P[o] = (x0 + x1 + x2 + x3) * 0.125f;
    }
    __syncthreads();

    // ---- softmax rows
    for (int t = tid; t < nwin*12; t += 256) {
        int w = t / 12, qi = t - w*12;
        float* row = &P[w*144 + qi*12];
        float mx = row[0];
        #pragma unroll
        for (int k2 = 1; k2 < 12; k2++) mx = fmaxf(mx, row[k2]);
        float sum = 0.f;
        float e[12];
        #pragma unroll
        for (int k2 = 0; k2 < 12; k2++) { e[k2] = __expf(row[k2] - mx); sum += e[k2]; }
        float inv = 1.f / sum;
        #pragma unroll
        for (int k2 = 0; k2 < 12; k2++) row[k2] = e[k2] * inv;
    }
    __syncthreads();

    // ---- write attention probabilities
    if (attn_out) {
        float* dst = attn_out + ((size_t)bh*NW + n0)*144;
        for (int o = tid; o < nwin*144; o += 256) dst[o] = P[o];
    }

    // ---- P @ V : 4 channels per work item, packed
    float* owp = &g_ow[((size_t)bh*NW + n0) * (WS*DH)];
    for (int o4 = tid; o4 < nwin*WS*16; o4 += 256) {
        int w = o4 / (WS*16);
        int r = o4 - w*(WS*16);
        int qi = r >> 4;
        int e4 = (r & 15) * 4;
        const float* prow = &P[w*144 + qi*12];
        const float* vb = &Vs[(w*6)*68 + e4];
        unsigned long long a01 = 0ULL, a23 = 0ULL;
        #pragma unroll
        for (int k2 = 0; k2 < 12; k2++) {
            float4 vv = *reinterpret_cast<const float4*>(&vb[k2*68]);
            unsigned long long pk = pack2(prow[k2], prow[k2]);
            a01 = ffma2(pk, pack2(vv.x, vv.y), a01);
            a23 = ffma2(pk, pack2(vv.z, vv.w), a23);
        }
        float o0, o1, o2, o3;
        unpack2(a01, o0, o1); unpack2(a23, o2, o3);
        *reinterpret_cast<float4*>(&owp[(size_t)w*(WS*DH) + qi*64 + e4]) =
            make_float4(o0, o1, o2, o3);
    }
}

// =============================================================================
// Kernel 3: overlap-add average + residual + LayerNorm
// =============================================================================
__global__ __launch_bounds__(128) void combine_kernel(
    const float* __restrict__ queries, const float* __restrict__ gamma,
    const float* __restrict__ beta, float* __restrict__ z)
{
    __shared__ float red[8];

    const int tid = threadIdx.x;
    const int tok = blockIdx.x;
    const int b = tok / LL;
    const int t = tok - b*LL;
    const int c0 = tid * 4;
    const int h = c0 >> 6;
    const int e = c0 & 63;

    const int n1 = t / 6, w1 = t - n1*6;
    const int n0 = n1 - 1, w0 = w1 + 6;

    float4 acc = make_float4(0.f, 0.f, 0.f, 0.f);
    float cnt = 0.f;
    if (n1 < NW) {
        const float* p = &g_ow[(((size_t)(b*HH + h)*NW + n1)*WS + w1)*64 + e];
        float4 v = *reinterpret_cast<const float4*>(p);
        acc.x += v.x; acc.y += v.y; acc.z += v.z; acc.w += v.w; cnt += 1.f;
    }
    if (n0 >= 0) {
        const float* p = &g_ow[(((size_t)(b*HH + h)*NW + n0)*WS + w0)*64 + e];
        float4 v = *reinterpret_cast<const float4*>(p);
        acc.x += v.x; acc.y += v.y; acc.z += v.z; acc.w += v.w; cnt += 1.f;
    }
    float inv = 1.f / cnt;
    float4 resid = *reinterpret_cast<const float4*>(&queries[(size_t)tok*DM + c0]);
    float4 x;
    x.x = acc.x*inv + resid.x; x.y = acc.y*inv + resid.y;
    x.z = acc.z*inv + resid.z; x.w = acc.w*inv + resid.w;

    float s  = x.x + x.y + x.z + x.w;
    float ss = x.x*x.x + x.y*x.y + x.z*x.z + x.w*x.w;
    #pragma unroll
    for (int off = 16; off > 0; off >>= 1) {
        s  += __shfl_down_sync(0xFFFFFFFFu, s, off);
        ss += __shfl_down_sync(0xFFFFFFFFu, ss, off);
    }
    int wid = tid >> 5, lane = tid & 31;
    if (lane == 0) { red[wid] = s; red[4 + wid] = ss; }
    __syncthreads();
    float ts  = red[0] + red[1] + red[2] + red[3];
    float tss = red[4] + red[5] + red[6] + red[7];
    float mean = ts * (1.f / DM);
    float var  = tss * (1.f / DM) - mean*mean;
    float rstd = rsqrtf(var + LNEPS);

    float4 g = *reinterpret_cast<const float4*>(&gamma[c0]);
    float4 bta = *reinterpret_cast<const float4*>(&beta[c0]);
    float4 o;
    o.x = (x.x - mean)*rstd*g.x + bta.x;
    o.y = (x.y - mean)*rstd*g.y + bta.y;
    o.z = (x.z - mean)*rstd*g.z + bta.z;
    o.w = (x.w - mean)*rstd*g.w + bta.w;
    *reinterpret_cast<float4*>(&z[(size_t)tok*DM + c0]) = o;
}

// =============================================================================
extern "C" void kernel_launch(void* const* d_in, const int* in_sizes, int n_in,
                              void* d_out, int out_size) {
    const float* queries = (const float*)d_in[0];
    const float* keys    = (const float*)d_in[1];
    const float* values  = (const float*)d_in[2];
    const float* Wq      = (const float*)d_in[3];
    const float* Wk      = (const float*)d_in[4];
    const float* Wv      = (const float*)d_in[5];
    const float* gamma   = (const float*)d_in[6];
    const float* beta    = (const float*)d_in[7];

    float* z = (float*)d_out;
    const long Z = (long)BB * LL * DM;
    const long A = (long)BB * HH * NW * WS * WS;
    float* attn_out = nullptr;
    if ((long)out_size >= Z + A) attn_out = z + Z;

    const int proj_smem = (64*136 + 64*68) * 4;             // 52224
    const int attn_smem = (3*54*68 + WB*144) * 4;           // 48672
    static bool attr_set = false;
    if (!attr_set) {
        cudaFuncSetAttribute(proj_kernel, cudaFuncAttributeMaxDynamicSharedMemorySize, proj_smem);
        cudaFuncSetAttribute(attn_kernel, cudaFuncAttributeMaxDynamicSharedMemorySize, attn_smem);
        attr_set = true;
    }

    dim3 pgrid(MROWS/128, 3);
    proj_kernel<<<pgrid, 128, proj_smem>>>(queries, keys, values, Wq, Wk, Wv);
    attn_kernel<<<BB*HH*NBLK_BH, 256, attn_smem>>>(attn_out);
    combine_kernel<<<BB*LL, 128>>>(queries, gamma, beta, z);
}

// round 6
// speedup vs baseline: 1.7347x; 1.0472x over previous
#include <cuda_runtime.h>
#include <cuda_bf16.h>
#include <mma.h>
#include <math.h>
#include <cstdint>

using namespace nvcuda;

// Problem constants
#define BB 4
#define LL 4092
#define HH 8
#define DH 64
#define DM 512
#define WS 12
#define STEP 6
#define NW 681
#define MROWS (BB*LL*HH)   // 130944
#define LNEPS 1e-5f
#define WB 8
#define NBLK_BH ((NW + WB - 1) / WB)   // 86

// ---------------- scratch -----------------
__device__ float g_Qp[BB*HH*LL*DH];
__device__ float g_Kp[BB*HH*LL*DH];
__device__ float g_Vp[BB*HH*LL*DH];
__device__ float g_ow[BB*HH*NW*WS*DH];

// ---------------- packed f32x2 helpers ----------------
__device__ __forceinline__ unsigned long long ffma2(
    unsigned long long a, unsigned long long b, unsigned long long c) {
    unsigned long long d;
    asm("fma.rn.f32x2 %0, %1, %2, %3;" : "=l"(d) : "l"(a), "l"(b), "l"(c));
    return d;
}
__device__ __forceinline__ unsigned long long pack2(float x, float y) {
    unsigned long long d;
    asm("mov.b64 %0, {%1, %2};" : "=l"(d)
        : "r"(__float_as_uint(x)), "r"(__float_as_uint(y)));
    return d;
}
__device__ __forceinline__ void unpack2(unsigned long long p, float& x, float& y) {
    unsigned int lo, hi;
    asm("mov.b64 {%0, %1}, %2;" : "=r"(lo), "=r"(hi) : "l"(p));
    x = __uint_as_float(lo); y = __uint_as_float(hi);
}

// =============================================================================
// Kernel 1: projections via wmma bf16 split (Ah*Bh + Ah*Bl + Al*Bh).
// grid = (1023, 3) : y selects matrix. 256 threads = 8 warps.
// Block computes 128 rows x 64 cols. Warp w -> rows [w*16, w*16+16).
// smem: sAh/sAl bf16[128][72], sBh/sBl bf16[64][72]; output staged over A.
// =============================================================================
#define A_STRIDE 72
#define B_STRIDE 72
#define SM_AH 0
#define SM_AL (128*A_STRIDE)                 // bf16 elements
#define SM_BH (2*128*A_STRIDE)
#define SM_BL (2*128*A_STRIDE + 64*B_STRIDE)
#define PROJ_SMEM_BF16 (2*128*A_STRIDE + 2*64*B_STRIDE)   // 27648 elems = 55296 B

__global__ __launch_bounds__(256) void proj_kernel(
    const float* __restrict__ q, const float* __restrict__ k, const float* __restrict__ v,
    const float* __restrict__ Wq, const float* __restrict__ Wk, const float* __restrict__ Wv)
{
    extern __shared__ __nv_bfloat16 smbf[];
    __nv_bfloat16* sAh = smbf + SM_AH;
    __nv_bfloat16* sAl = smbf + SM_AL;
    __nv_bfloat16* sBh = smbf + SM_BH;
    __nv_bfloat16* sBl = smbf + SM_BL;
    float* sOut = reinterpret_cast<float*>(smbf);    // reuse A region (32 KB < 36.9 KB)

    const int tid = threadIdx.x;
    const int warp = tid >> 5;
    const int r0 = blockIdx.x * 128;
    const int m  = blockIdx.y;

    const float* X = (m == 0) ? q : (m == 1) ? k : v;
    const float* W = (m == 0) ? Wq : (m == 1) ? Wk : Wv;
    float* Out = (m == 0) ? g_Qp : (m == 1) ? g_Kp : g_Vp;

    // ---- W -> bf16 hi/lo, transposed: sB*[d][e] = W[e][d]
    for (int idx = tid; idx < 4096; idx += 256) {
        int e = idx >> 6, d = idx & 63;
        float w = W[idx];
        __nv_bfloat16 hi = __float2bfloat16(w);
        __nv_bfloat16 lo = __float2bfloat16(w - __bfloat162float(hi));
        sBh[d*B_STRIDE + e] = hi;
        sBl[d*B_STRIDE + e] = lo;
    }
    // ---- X -> bf16 hi/lo, row-major [128][72]
    for (int idx = tid; idx < 2048; idx += 256) {      // 2048 float4
        int row = idx >> 4, c4 = idx & 15;
        float4 xv = reinterpret_cast<const float4*>(X + (size_t)(r0 + row)*64)[c4];
        float xs[4] = {xv.x, xv.y, xv.z, xv.w};
        #pragma unroll
        for (int j = 0; j < 4; j++) {
            __nv_bfloat16 hi = __float2bfloat16(xs[j]);
            __nv_bfloat16 lo = __float2bfloat16(xs[j] - __bfloat162float(hi));
            sAh[row*A_STRIDE + c4*4 + j] = hi;
            sAl[row*A_STRIDE + c4*4 + j] = lo;
        }
    }
    __syncthreads();

    // ---- load this warp's A fragments (4 k-tiles, hi+lo)
    wmma::fragment<wmma::matrix_a, 16, 16, 16, __nv_bfloat16, wmma::row_major> a_hi[4], a_lo[4];
    #pragma unroll
    for (int kk = 0; kk < 4; kk++) {
        wmma::load_matrix_sync(a_hi[kk], &sAh[(warp*16)*A_STRIDE + kk*16], A_STRIDE);
        wmma::load_matrix_sync(a_lo[kk], &sAl[(warp*16)*A_STRIDE + kk*16], A_STRIDE);
    }
    __syncthreads();   // all A fragments in registers before staging overwrites sA*

    // ---- MMA: 4 n-tiles, each 4 k-tiles x 3 split-terms
    #pragma unroll
    for (int n = 0; n < 4; n++) {
        wmma::fragment<wmma::accumulator, 16, 16, 16, float> acc;
        wmma::fill_fragment(acc, 0.0f);
        #pragma unroll
        for (int kk = 0; kk < 4; kk++) {
            wmma::fragment<wmma::matrix_b, 16, 16, 16, __nv_bfloat16, wmma::row_major> b_hi, b_lo;
            wmma::load_matrix_sync(b_hi, &sBh[(kk*16)*B_STRIDE + n*16], B_STRIDE);
            wmma::load_matrix_sync(b_lo, &sBl[(kk*16)*B_STRIDE + n*16], B_STRIDE);
            wmma::mma_sync(acc, a_hi[kk], b_hi, acc);
            wmma::mma_sync(acc, a_hi[kk], b_lo, acc);
            wmma::mma_sync(acc, a_lo[kk], b_hi, acc);
        }
        wmma::store_matrix_sync(&sOut[(warp*16)*64 + n*16], acc, 64, wmma::mem_row_major);
    }
    __syncthreads();

    // ---- scatter rows to [B,H,L,64]
    for (int idx = tid; idx < 2048; idx += 256) {
        int row = idx >> 4, c4 = idx & 15;
        int r = r0 + row;
        int b = r / (LL*HH);
        int rem = r - b*(LL*HH);
        int l = rem >> 3;
        int h = rem & 7;
        float* orow = Out + ((size_t)(b*HH + h)*LL + l)*64;
        *reinterpret_cast<float4*>(orow + c4*4) =
            *reinterpret_cast<const float4*>(&sOut[row*64 + c4*4]);
    }
}

// =============================================================================
// Kernel 2: attention, WB windows per block, 256 threads, packed math.
// =============================================================================
__global__ __launch_bounds__(256) void attn_kernel(float* __restrict__ attn_out)
{
    extern __shared__ float sm[];
    float* Qs = sm;                 // 54*68
    float* Ks = Qs + 54*68;
    float* Vs = Ks + 54*68;
    float* P  = Vs + 54*68;         // WB*144

    const int tid = threadIdx.x;
    const int blk = blockIdx.x;
    const int bh = blk / NBLK_BH;
    const int ng = blk - bh * NBLK_BH;
    const int n0 = ng * WB;
    const int nwin = (NW - n0 < WB) ? (NW - n0) : WB;
    const int rows = nwin*6 + 6;

    const size_t base = ((size_t)bh * LL + n0*STEP) * 64;

    {
        const float* srcs[3] = {g_Qp + base, g_Kp + base, g_Vp + base};
        float* dsts[3] = {Qs, Ks, Vs};
        int nf4 = rows * 16;
        #pragma unroll
        for (int m = 0; m < 3; m++) {
            const float4* src = reinterpret_cast<const float4*>(srcs[m]);
            float* dst = dsts[m];
            for (int idx = tid; idx < nf4; idx += 256) {
                int row = idx >> 4, c4 = idx & 15;
                float4 val = src[idx];
                *reinterpret_cast<float4*>(&dst[row*68 + c4*4]) = val;
            }
        }
    }
    __syncthreads();

    for (int o = tid; o < nwin*144; o += 256) {
        int w = o / 144;
        int r = o - w*144;
        int qi = r / 12, ki = r - qi*12;
        const float* qr = &Qs[(w*6 + qi)*68];
        const float* kr = &Ks[(w*6 + ki)*68];
        unsigned long long s01 = 0ULL, s23 = 0ULL;
        #pragma unroll
        for (int d = 0; d < 64; d += 4) {
            float4 a = *reinterpret_cast<const float4*>(&qr[d]);
            float4 b = *reinterpret_cast<const float4*>(&kr[d]);
            s01 = ffma2(pack2(a.x, a.y), pack2(b.x, b.y), s01);
            s23 = ffma2(pack2(a.z, a.w), pack2(b.z, b.w), s23);
        }
        float x0, x1, x2, x3;
        unpack2(s01, x0, x1); unpack2(s23, x2, x3);
        P[o] = (x0 + x1 + x2 + x3) * 0.125f;
    }
    __syncthreads();

    for (int t = tid; t < nwin*12; t += 256) {
        int w = t / 12, qi = t - w*12;
        float* row = &P[w*144 + qi*12];
        float mx = row[0];
        #pragma unroll
        for (int k2 = 1; k2 < 12; k2++) mx = fmaxf(mx, row[k2]);
        float sum = 0.f;
        float e[12];
        #pragma unroll
        for (int k2 = 0; k2 < 12; k2++) { e[k2] = __expf(row[k2] - mx); sum += e[k2]; }
        float inv = 1.f / sum;
        #pragma unroll
        for (int k2 = 0; k2 < 12; k2++) row[k2] = e[k2] * inv;
    }
    __syncthreads();

    if (attn_out) {
        float* dst = attn_out + ((size_t)bh*NW + n0)*144;
        for (int o = tid; o < nwin*144; o += 256) dst[o] = P[o];
    }

    float* owp = &g_ow[((size_t)bh*NW + n0) * (WS*DH)];
    for (int o4 = tid; o4 < nwin*WS*16; o4 += 256) {
        int w = o4 / (WS*16);
        int r = o4 - w*(WS*16);
        int qi = r >> 4;
        int e4 = (r & 15) * 4;
        const float* prow = &P[w*144 + qi*12];
        const float* vb = &Vs[(w*6)*68 + e4];
        unsigned long long a01 = 0ULL, a23 = 0ULL;
        #pragma unroll
        for (int k2 = 0; k2 < 12; k2++) {
            float4 vv = *reinterpret_cast<const float4*>(&vb[k2*68]);
            unsigned long long pk = pack2(prow[k2], prow[k2]);
            a01 = ffma2(pk, pack2(vv.x, vv.y), a01);
            a23 = ffma2(pk, pack2(vv.z, vv.w), a23);
        }
        float o0, o1, o2, o3;
        unpack2(a01, o0, o1); unpack2(a23, o2, o3);
        *reinterpret_cast<float4*>(&owp[(size_t)w*(WS*DH) + qi*64 + e4]) =
            make_float4(o0, o1, o2, o3);
    }
}

// =============================================================================
// Kernel 3: overlap-add average + residual + LayerNorm
// =============================================================================
__global__ __launch_bounds__(128) void combine_kernel(
    const float* __restrict__ queries, const float* __restrict__ gamma,
    const float* __restrict__ beta, float* __restrict__ z)
{
    __shared__ float red[8];

    const int tid = threadIdx.x;
    const int tok = blockIdx.x;
    const int b = tok / LL;
    const int t = tok - b*LL;
    const int c0 = tid * 4;
    const int h = c0 >> 6;
    const int e = c0 & 63;

    const int n1 = t / 6, w1 = t - n1*6;
    const int n0 = n1 - 1, w0 = w1 + 6;

    float4 acc = make_float4(0.f, 0.f, 0.f, 0.f);
    float cnt = 0.f;
    if (n1 < NW) {
        const float* p = &g_ow[(((size_t)(b*HH + h)*NW + n1)*WS + w1)*64 + e];
        float4 v = *reinterpret_cast<const float4*>(p);
        acc.x += v.x; acc.y += v.y; acc.z += v.z; acc.w += v.w; cnt += 1.f;
    }
    if (n0 >= 0) {
        const float* p = &g_ow[(((size_t)(b*HH + h)*NW + n0)*WS + w0)*64 + e];
        float4 v = *reinterpret_cast<const float4*>(p);
        acc.x += v.x; acc.y += v.y; acc.z += v.z; acc.w += v.w; cnt += 1.f;
    }
    float inv = 1.f / cnt;
    float4 resid = *reinterpret_cast<const float4*>(&queries[(size_t)tok*DM + c0]);
    float4 x;
    x.x = acc.x*inv + resid.x; x.y = acc.y*inv + resid.y;
    x.z = acc.z*inv + resid.z; x.w = acc.w*inv + resid.w;

    float s  = x.x + x.y + x.z + x.w;
    float ss = x.x*x.x + x.y*x.y + x.z*x.z + x.w*x.w;
    #pragma unroll
    for (int off = 16; off > 0; off >>= 1) {
        s  += __shfl_down_sync(0xFFFFFFFFu, s, off);
        ss += __shfl_down_sync(0xFFFFFFFFu, ss, off);
    }
    int wid = tid >> 5, lane = tid & 31;
    if (lane == 0) { red[wid] = s; red[4 + wid] = ss; }
    __syncthreads();
    float ts  = red[0] + red[1] + red[2] + red[3];
    float tss = red[4] + red[5] + red[6] + red[7];
    float mean = ts * (1.f / DM);
    float var  = tss * (1.f / DM) - mean*mean;
    float rstd = rsqrtf(var + LNEPS);

    float4 g = *reinterpret_cast<const float4*>(&gamma[c0]);
    float4 bta = *reinterpret_cast<const float4*>(&beta[c0]);
    float4 o;
    o.x = (x.x - mean)*rstd*g.x + bta.x;
    o.y = (x.y - mean)*rstd*g.y + bta.y;
    o.z = (x.z - mean)*rstd*g.z + bta.z;
    o.w = (x.w - mean)*rstd*g.w + bta.w;
    *reinterpret_cast<float4*>(&z[(size_t)tok*DM + c0]) = o;
}

// =============================================================================
extern "C" void kernel_launch(void* const* d_in, const int* in_sizes, int n_in,
                              void* d_out, int out_size) {
    const float* queries = (const float*)d_in[0];
    const float* keys    = (const float*)d_in[1];
    const float* values  = (const float*)d_in[2];
    const float* Wq      = (const float*)d_in[3];
    const float* Wk      = (const float*)d_in[4];
    const float* Wv      = (const float*)d_in[5];
    const float* gamma   = (const float*)d_in[6];
    const float* beta    = (const float*)d_in[7];

    float* z = (float*)d_out;
    const long Z = (long)BB * LL * DM;
    const long A = (long)BB * HH * NW * WS * WS;
    float* attn_out = nullptr;
    if ((long)out_size >= Z + A) attn_out = z + Z;

    const int proj_smem = PROJ_SMEM_BF16 * 2;               // 55296 B
    const int attn_smem = (3*54*68 + WB*144) * 4;           // 48672 B
    static bool attr_set = false;
    if (!attr_set) {
        cudaFuncSetAttribute(proj_kernel, cudaFuncAttributeMaxDynamicSharedMemorySize, proj_smem);
        cudaFuncSetAttribute(attn_kernel, cudaFuncAttributeMaxDynamicSharedMemorySize, attn_smem);
        attr_set = true;
    }

    dim3 pgrid(MROWS/128, 3);
    proj_kernel<<<pgrid, 256, proj_smem>>>(queries, keys, values, Wq, Wk, Wv);
    attn_kernel<<<BB*HH*NBLK_BH, 256, attn_smem>>>(attn_out);
    combine_kernel<<<BB*LL, 128>>>(queries, gamma, beta, z);
}

// round 7
// speedup vs baseline: 1.8973x; 1.0937x over previous
#include <cuda_runtime.h>
#include <cuda_bf16.h>
#include <mma.h>
#include <math.h>
#include <cstdint>

using namespace nvcuda;

// Problem constants
#define BB 4
#define LL 4092
#define HH 8
#define DH 64
#define DM 512
#define WS 12
#define STEP 6
#define NW 681
#define MROWS (BB*LL*HH)   // 130944
#define LNEPS 1e-5f
#define WB 8
#define NBLK_BH ((NW + WB - 1) / WB)   // 86

// ---------------- scratch (natural [B,L,H,64] layout now) -----------------
__device__ float g_Qp[MROWS*DH];
__device__ float g_Kp[MROWS*DH];
__device__ float g_Vp[MROWS*DH];
__device__ float g_ow[BB*HH*NW*WS*DH];

// ---------------- packed f32x2 helpers ----------------
__device__ __forceinline__ unsigned long long ffma2(
    unsigned long long a, unsigned long long b, unsigned long long c) {
    unsigned long long d;
    asm("fma.rn.f32x2 %0, %1, %2, %3;" : "=l"(d) : "l"(a), "l"(b), "l"(c));
    return d;
}
__device__ __forceinline__ unsigned long long pack2(float x, float y) {
    unsigned long long d;
    asm("mov.b64 %0, {%1, %2};" : "=l"(d)
        : "r"(__float_as_uint(x)), "r"(__float_as_uint(y)));
    return d;
}
__device__ __forceinline__ void unpack2(unsigned long long p, float& x, float& y) {
    unsigned int lo, hi;
    asm("mov.b64 {%0, %1}, %2;" : "=r"(lo), "=r"(hi) : "l"(p));
    x = __uint_as_float(lo); y = __uint_as_float(hi);
}

// =============================================================================
// Kernel 1: projections via wmma bf16 split (Ah*Bh + Ah*Bl + Al*Bh).
// grid = (1023, 3). 256 threads = 8 warps; warp w -> rows [w*16, w*16+16).
// Output written DIRECTLY to global in natural [M][64] layout from fragments.
// =============================================================================
#define A_STRIDE 72
#define B_STRIDE 72
#define SM_AH 0
#define SM_AL (128*A_STRIDE)
#define SM_BH (2*128*A_STRIDE)
#define SM_BL (2*128*A_STRIDE + 64*B_STRIDE)
#define PROJ_SMEM_BF16 (2*128*A_STRIDE + 2*64*B_STRIDE)   // 27648 elems = 55296 B

__global__ __launch_bounds__(256) void proj_kernel(
    const float* __restrict__ q, const float* __restrict__ k, const float* __restrict__ v,
    const float* __restrict__ Wq, const float* __restrict__ Wk, const float* __restrict__ Wv)
{
    extern __shared__ __nv_bfloat16 smbf[];
    __nv_bfloat16* sAh = smbf + SM_AH;
    __nv_bfloat16* sAl = smbf + SM_AL;
    __nv_bfloat16* sBh = smbf + SM_BH;
    __nv_bfloat16* sBl = smbf + SM_BL;

    const int tid = threadIdx.x;
    const int warp = tid >> 5;
    const int r0 = blockIdx.x * 128;
    const int m  = blockIdx.y;

    const float* X = (m == 0) ? q : (m == 1) ? k : v;
    const float* W = (m == 0) ? Wq : (m == 1) ? Wk : Wv;
    float* Out = (m == 0) ? g_Qp : (m == 1) ? g_Kp : g_Vp;

    // ---- W -> bf16 hi/lo, transposed: sB*[d][e] = W[e][d]
    for (int idx = tid; idx < 4096; idx += 256) {
        int e = idx >> 6, d = idx & 63;
        float w = W[idx];
        __nv_bfloat16 hi = __float2bfloat16(w);
        __nv_bfloat16 lo = __float2bfloat16(w - __bfloat162float(hi));
        sBh[d*B_STRIDE + e] = hi;
        sBl[d*B_STRIDE + e] = lo;
    }
    // ---- X -> bf16 hi/lo, row-major [128][72]
    for (int idx = tid; idx < 2048; idx += 256) {      // 2048 float4
        int row = idx >> 4, c4 = idx & 15;
        float4 xv = reinterpret_cast<const float4*>(X + (size_t)(r0 + row)*64)[c4];
        float xs[4] = {xv.x, xv.y, xv.z, xv.w};
        #pragma unroll
        for (int j = 0; j < 4; j++) {
            __nv_bfloat16 hi = __float2bfloat16(xs[j]);
            __nv_bfloat16 lo = __float2bfloat16(xs[j] - __bfloat162float(hi));
            sAh[row*A_STRIDE + c4*4 + j] = hi;
            sAl[row*A_STRIDE + c4*4 + j] = lo;
        }
    }
    __syncthreads();

    // ---- load this warp's A fragments (4 k-tiles, hi+lo)
    wmma::fragment<wmma::matrix_a, 16, 16, 16, __nv_bfloat16, wmma::row_major> a_hi[4], a_lo[4];
    #pragma unroll
    for (int kk = 0; kk < 4; kk++) {
        wmma::load_matrix_sync(a_hi[kk], &sAh[(warp*16)*A_STRIDE + kk*16], A_STRIDE);
        wmma::load_matrix_sync(a_lo[kk], &sAl[(warp*16)*A_STRIDE + kk*16], A_STRIDE);
    }

    // ---- MMA: 4 n-tiles; store straight to global (natural row-major [M][64])
    float* wOut = Out + (size_t)(r0 + warp*16) * 64;
    #pragma unroll
    for (int n = 0; n < 4; n++) {
        wmma::fragment<wmma::accumulator, 16, 16, 16, float> acc;
        wmma::fill_fragment(acc, 0.0f);
        #pragma unroll
        for (int kk = 0; kk < 4; kk++) {
            wmma::fragment<wmma::matrix_b, 16, 16, 16, __nv_bfloat16, wmma::row_major> b_hi, b_lo;
            wmma::load_matrix_sync(b_hi, &sBh[(kk*16)*B_STRIDE + n*16], B_STRIDE);
            wmma::load_matrix_sync(b_lo, &sBl[(kk*16)*B_STRIDE + n*16], B_STRIDE);
            wmma::mma_sync(acc, a_hi[kk], b_hi, acc);
            wmma::mma_sync(acc, a_hi[kk], b_lo, acc);
            wmma::mma_sync(acc, a_lo[kk], b_hi, acc);
        }
        wmma::store_matrix_sync(wOut + n*16, acc, 64, wmma::mem_row_major);
    }
}

// =============================================================================
// Kernel 2: attention, WB windows per block, 256 threads, packed math.
// Projected Q/K/V now in natural [B,L,H,64] layout: row stride = 512 floats.
// =============================================================================
__global__ __launch_bounds__(256) void attn_kernel(float* __restrict__ attn_out)
{
    extern __shared__ float sm[];
    float* Qs = sm;                 // 54*68
    float* Ks = Qs + 54*68;
    float* Vs = Ks + 54*68;
    float* P  = Vs + 54*68;         // WB*144

    const int tid = threadIdx.x;
    const int blk = blockIdx.x;
    const int bh = blk / NBLK_BH;
    const int ng = blk - bh * NBLK_BH;
    const int b  = bh >> 3;
    const int h  = bh & 7;
    const int n0 = ng * WB;
    const int nwin = (NW - n0 < WB) ? (NW - n0) : WB;
    const int rows = nwin*6 + 6;
    const int t0 = n0 * STEP;

    // base offset of (b, t0, h, 0) in [B,L,H,64]; row stride = HH*64 = 512
    const size_t base = ((size_t)(b*LL + t0)*HH + h) * 64;

    {
        const float* srcs[3] = {g_Qp + base, g_Kp + base, g_Vp + base};
        float* dsts[3] = {Qs, Ks, Vs};
        int nf4 = rows * 16;
        #pragma unroll
        for (int m = 0; m < 3; m++) {
            const float* src = srcs[m];
            float* dst = dsts[m];
            for (int idx = tid; idx < nf4; idx += 256) {
                int row = idx >> 4, c4 = idx & 15;
                float4 val = *reinterpret_cast<const float4*>(src + (size_t)row*512 + c4*4);
                *reinterpret_cast<float4*>(&dst[row*68 + c4*4]) = val;
            }
        }
    }
    __syncthreads();

    for (int o = tid; o < nwin*144; o += 256) {
        int w = o / 144;
        int r = o - w*144;
        int qi = r / 12, ki = r - qi*12;
        const float* qr = &Qs[(w*6 + qi)*68];
        const float* kr = &Ks[(w*6 + ki)*68];
        unsigned long long s01 = 0ULL, s23 = 0ULL;
        #pragma unroll
        for (int d = 0; d < 64; d += 4) {
            float4 a = *reinterpret_cast<const float4*>(&qr[d]);
            float4 bb = *reinterpret_cast<const float4*>(&kr[d]);
            s01 = ffma2(pack2(a.x, a.y), pack2(bb.x, bb.y), s01);
            s23 = ffma2(pack2(a.z, a.w), pack2(bb.z, bb.w), s23);
        }
        float x0, x1, x2, x3;
        unpack2(s01, x0, x1); unpack2(s23, x2, x3);
        P[o] = (x0 + x1 + x2 + x3) * 0.125f;
    }
    __syncthreads();

    for (int t = tid; t < nwin*12; t += 256) {
        int w = t / 12, qi = t - w*12;
        float* row = &P[w*144 + qi*12];
        float mx = row[0];
        #pragma unroll
        for (int k2 = 1; k2 < 12; k2++) mx = fmaxf(mx, row[k2]);
        float sum = 0.f;
        float e[12];
        #pragma unroll
        for (int k2 = 0; k2 < 12; k2++) { e[k2] = __expf(row[k2] - mx); sum += e[k2]; }
        float inv = 1.f / sum;
        #pragma unroll
        for (int k2 = 0; k2 < 12; k2++) row[k2] = e[k2] * inv;
    }
    __syncthreads();

    if (attn_out) {
        float* dst = attn_out + ((size_t)bh*NW + n0)*144;
        for (int o = tid; o < nwin*144; o += 256) dst[o] = P[o];
    }

    float* owp = &g_ow[((size_t)bh*NW + n0) * (WS*DH)];
    for (int o4 = tid; o4 < nwin*WS*16; o4 += 256) {
        int w = o4 / (WS*16);
        int r = o4 - w*(WS*16);
        int qi = r >> 4;
        int e4 = (r & 15) * 4;
        const float* prow = &P[w*144 + qi*12];
        const float* vb = &Vs[(w*6)*68 + e4];
        unsigned long long a01 = 0ULL, a23 = 0ULL;
        #pragma unroll
        for (int k2 = 0; k2 < 12; k2++) {
            float4 vv = *reinterpret_cast<const float4*>(&vb[k2*68]);
            unsigned long long pk = pack2(prow[k2], prow[k2]);
            a01 = ffma2(pk, pack2(vv.x, vv.y), a01);
            a23 = ffma2(pk, pack2(vv.z, vv.w), a23);
        }
        float o0, o1, o2, o3;
        unpack2(a01, o0, o1); unpack2(a23, o2, o3);
        *reinterpret_cast<float4*>(&owp[(size_t)w*(WS*DH) + qi*64 + e4]) =
            make_float4(o0, o1, o2, o3);
    }
}

// =============================================================================
// Kernel 3: overlap-add average + residual + LayerNorm
// =============================================================================
__global__ __launch_bounds__(128) void combine_kernel(
    const float* __restrict__ queries, const float* __restrict__ gamma,
    const float* __restrict__ beta, float* __restrict__ z)
{
    __shared__ float red[8];

    const int tid = threadIdx.x;
    const int tok = blockIdx.x;
    const int b = tok / LL;
    const int t = tok - b*LL;
    const int c0 = tid * 4;
    const int h = c0 >> 6;
    const int e = c0 & 63;

    const int n1 = t / 6, w1 = t - n1*6;
    const int n0 = n1 - 1, w0 = w1 + 6;

    float4 acc = make_float4(0.f, 0.f, 0.f, 0.f);
    float cnt = 0.f;
    if (n1 < NW) {
        const float* p = &g_ow[(((size_t)(b*HH + h)*NW + n1)*WS + w1)*64 + e];
        float4 v = *reinterpret_cast<const float4*>(p);
        acc.x += v.x; acc.y += v.y; acc.z += v.z; acc.w += v.w; cnt += 1.f;
    }
    if (n0 >= 0) {
        const float* p = &g_ow[(((size_t)(b*HH + h)*NW + n0)*WS + w0)*64 + e];
        float4 v = *reinterpret_cast<const float4*>(p);
        acc.x += v.x; acc.y += v.y; acc.z += v.z; acc.w += v.w; cnt += 1.f;
    }
    float inv = 1.f / cnt;
    float4 resid = *reinterpret_cast<const float4*>(&queries[(size_t)tok*DM + c0]);
    float4 x;
    x.x = acc.x*inv + resid.x; x.y = acc.y*inv + resid.y;
    x.z = acc.z*inv + resid.z; x.w = acc.w*inv + resid.w;

    float s  = x.x + x.y + x.z + x.w;
    float ss = x.x*x.x + x.y*x.y + x.z*x.z + x.w*x.w;
    #pragma unroll
    for (int off = 16; off > 0; off >>= 1) {
        s  += __shfl_down_sync(0xFFFFFFFFu, s, off);
        ss += __shfl_down_sync(0xFFFFFFFFu, ss, off);
    }
    int wid = tid >> 5, lane = tid & 31;
    if (lane == 0) { red[wid] = s; red[4 + wid] = ss; }
    __syncthreads();
    float ts  = red[0] + red[1] + red[2] + red[3];
    float tss = red[4] + red[5] + red[6] + red[7];
    float mean = ts * (1.f / DM);
    float var  = tss * (1.f / DM) - mean*mean;
    float rstd = rsqrtf(var + LNEPS);

    float4 g = *reinterpret_cast<const float4*>(&gamma[c0]);
    float4 bta = *reinterpret_cast<const float4*>(&beta[c0]);
    float4 o;
    o.x = (x.x - mean)*rstd*g.x + bta.x;
    o.y = (x.y - mean)*rstd*g.y + bta.y;
    o.z = (x.z - mean)*rstd*g.z + bta.z;
    o.w = (x.w - mean)*rstd*g.w + bta.w;
    *reinterpret_cast<float4*>(&z[(size_t)tok*DM + c0]) = o;
}

// =============================================================================
extern "C" void kernel_launch(void* const* d_in, const int* in_sizes, int n_in,
                              void* d_out, int out_size) {
    const float* queries = (const float*)d_in[0];
    const float* keys    = (const float*)d_in[1];
    const float* values  = (const float*)d_in[2];
    const float* Wq      = (const float*)d_in[3];
    const float* Wk      = (const float*)d_in[4];
    const float* Wv      = (const float*)d_in[5];
    const float* gamma   = (const float*)d_in[6];
    const float* beta    = (const float*)d_in[7];

    float* z = (float*)d_out;
    const long Z = (long)BB * LL * DM;
    const long A = (long)BB * HH * NW * WS * WS;
    float* attn_out = nullptr;
    if ((long)out_size >= Z + A) attn_out = z + Z;

    const int proj_smem = PROJ_SMEM_BF16 * 2;               // 55296 B
    const int attn_smem = (3*54*68 + WB*144) * 4;           // 48672 B
    static bool attr_set = false;
    if (!attr_set) {
        cudaFuncSetAttribute(proj_kernel, cudaFuncAttributeMaxDynamicSharedMemorySize, proj_smem);
        cudaFuncSetAttribute(attn_kernel, cudaFuncAttributeMaxDynamicSharedMemorySize, attn_smem);
        attr_set = true;
    }

    dim3 pgrid(MROWS/128, 3);
    proj_kernel<<<pgrid, 256, proj_smem>>>(queries, keys, values, Wq, Wk, Wv);
    attn_kernel<<<BB*HH*NBLK_BH, 256, attn_smem>>>(attn_out);
    combine_kernel<<<BB*LL, 128>>>(queries, gamma, beta, z);
}

// round 8
// speedup vs baseline: 2.0829x; 1.0978x over previous
#include <cuda_runtime.h>
#include <cuda_bf16.h>
#include <mma.h>
#include <math.h>
#include <cstdint>

using namespace nvcuda;

// Problem constants
#define BB 4
#define LL 4092
#define HH 8
#define DH 64
#define DM 512
#define WS 12
#define STEP 6
#define NW 681
#define MROWS (BB*LL*HH)   // 130944
#define LNEPS 1e-5f
// attn tiling: finalize 7 windows (42 tokens) per block, load 8 (1 halo)
#define TPB_TOK 42
#define NG 98              // ceil(4092/42)

// ---------------- scratch -----------------
__device__ float g_Qp[MROWS*DH];          // [B,L,H,64]
__device__ float g_Kp[MROWS*DH];
__device__ float g_Vp[MROWS*DH];
__device__ float g_att[BB*LL*DM];         // finalized averaged attn out [B,L,H*64]
__device__ __nv_bfloat16 g_Wh[3*64*64];   // transposed [m][d][e] bf16 hi
__device__ __nv_bfloat16 g_Wl[3*64*64];   // transposed [m][d][e] bf16 lo

// ---------------- packed f32x2 helpers ----------------
__device__ __forceinline__ unsigned long long ffma2(
    unsigned long long a, unsigned long long b, unsigned long long c) {
    unsigned long long d;
    asm("fma.rn.f32x2 %0, %1, %2, %3;" : "=l"(d) : "l"(a), "l"(b), "l"(c));
    return d;
}
__device__ __forceinline__ unsigned long long pack2(float x, float y) {
    unsigned long long d;
    asm("mov.b64 %0, {%1, %2};" : "=l"(d)
        : "r"(__float_as_uint(x)), "r"(__float_as_uint(y)));
    return d;
}
__device__ __forceinline__ void unpack2(unsigned long long p, float& x, float& y) {
    unsigned int lo, hi;
    asm("mov.b64 {%0, %1}, %2;" : "=r"(lo), "=r"(hi) : "l"(p));
    x = __uint_as_float(lo); y = __uint_as_float(hi);
}

// =============================================================================
// Kernel 0: W -> transposed bf16 hi/lo. grid = 3 blocks (one per matrix).
// =============================================================================
__global__ __launch_bounds__(256) void prep_kernel(
    const float* __restrict__ Wq, const float* __restrict__ Wk, const float* __restrict__ Wv)
{
    const int m = blockIdx.x;
    const float* W = (m == 0) ? Wq : (m == 1) ? Wk : Wv;
    for (int idx = threadIdx.x; idx < 4096; idx += 256) {
        int e = idx >> 6, d = idx & 63;
        float w = W[idx];
        __nv_bfloat16 hi = __float2bfloat16(w);
        __nv_bfloat16 lo = __float2bfloat16(w - __bfloat162float(hi));
        g_Wh[m*4096 + d*64 + e] = hi;
        g_Wl[m*4096 + d*64 + e] = lo;
    }
}

// =============================================================================
// Kernel 1: projections via wmma bf16 split. grid = (1023, 3). 256 thr.
// =============================================================================
#define A_STRIDE 72
#define B_STRIDE 72
#define SM_AH 0
#define SM_AL (128*A_STRIDE)
#define SM_BH (2*128*A_STRIDE)
#define SM_BL (2*128*A_STRIDE + 64*B_STRIDE)
#define PROJ_SMEM_BF16 (2*128*A_STRIDE + 2*64*B_STRIDE)   // 55296 B

__global__ __launch_bounds__(256) void proj_kernel(
    const float* __restrict__ q, const float* __restrict__ k, const float* __restrict__ v)
{
    extern __shared__ __nv_bfloat16 smbf[];
    __nv_bfloat16* sAh = smbf + SM_AH;
    __nv_bfloat16* sAl = smbf + SM_AL;
    __nv_bfloat16* sBh = smbf + SM_BH;
    __nv_bfloat16* sBl = smbf + SM_BL;

    const int tid = threadIdx.x;
    const int warp = tid >> 5;
    const int r0 = blockIdx.x * 128;
    const int m  = blockIdx.y;

    const float* X = (m == 0) ? q : (m == 1) ? k : v;
    float* Out = (m == 0) ? g_Qp : (m == 1) ? g_Kp : g_Vp;

    // ---- copy precomputed W (transposed bf16) into smem, uint2 = 4 bf16
    {
        const uint2* srcH = reinterpret_cast<const uint2*>(g_Wh + m*4096);
        const uint2* srcL = reinterpret_cast<const uint2*>(g_Wl + m*4096);
        for (int idx = tid; idx < 1024; idx += 256) {
            int d = idx >> 4, c4 = idx & 15;     // 16 uint2 per 64-elem row
            *reinterpret_cast<uint2*>(&sBh[d*B_STRIDE + c4*4]) = srcH[idx];
            *reinterpret_cast<uint2*>(&sBl[d*B_STRIDE + c4*4]) = srcL[idx];
        }
    }
    // ---- X -> bf16 hi/lo, row-major [128][72]
    for (int idx = tid; idx < 2048; idx += 256) {      // 2048 float4
        int row = idx >> 4, c4 = idx & 15;
        float4 xv = reinterpret_cast<const float4*>(X + (size_t)(r0 + row)*64)[c4];
        float xs[4] = {xv.x, xv.y, xv.z, xv.w};
        #pragma unroll
        for (int j = 0; j < 4; j++) {
            __nv_bfloat16 hi = __float2bfloat16(xs[j]);
            __nv_bfloat16 lo = __float2bfloat16(xs[j] - __bfloat162float(hi));
            sAh[row*A_STRIDE + c4*4 + j] = hi;
            sAl[row*A_STRIDE + c4*4 + j] = lo;
        }
    }
    __syncthreads();

    // ---- A fragments
    wmma::fragment<wmma::matrix_a, 16, 16, 16, __nv_bfloat16, wmma::row_major> a_hi[4], a_lo[4];
    #pragma unroll
    for (int kk = 0; kk < 4; kk++) {
        wmma::load_matrix_sync(a_hi[kk], &sAh[(warp*16)*A_STRIDE + kk*16], A_STRIDE);
        wmma::load_matrix_sync(a_lo[kk], &sAl[(warp*16)*A_STRIDE + kk*16], A_STRIDE);
    }

    // ---- MMA, store straight to global [M][64]
    float* wOut = Out + (size_t)(r0 + warp*16) * 64;
    #pragma unroll
    for (int n = 0; n < 4; n++) {
        wmma::fragment<wmma::accumulator, 16, 16, 16, float> acc;
        wmma::fill_fragment(acc, 0.0f);
        #pragma unroll
        for (int kk = 0; kk < 4; kk++) {
            wmma::fragment<wmma::matrix_b, 16, 16, 16, __nv_bfloat16, wmma::row_major> b_hi, b_lo;
            wmma::load_matrix_sync(b_hi, &sBh[(kk*16)*B_STRIDE + n*16], B_STRIDE);
            wmma::load_matrix_sync(b_lo, &sBl[(kk*16)*B_STRIDE + n*16], B_STRIDE);
            wmma::mma_sync(acc, a_hi[kk], b_hi, acc);
            wmma::mma_sync(acc, a_hi[kk], b_lo, acc);
            wmma::mma_sync(acc, a_lo[kk], b_hi, acc);
        }
        wmma::store_matrix_sync(wOut + n*16, acc, 64, wmma::mem_row_major);
    }
}

// =============================================================================
// Kernel 2: attention + overlap-add finalization.
// Block (bh, g): loads windows [n_lo, n_hi] (<= 8, 1 halo), finalizes the 42
// tokens [g*42, g*42+42) with both window contributions in-block, writes
// averaged per-head output to g_att[B,L,H,64]. Writes probs for n in
// [7g, 7g+7) (disjoint across g).
// =============================================================================
__global__ __launch_bounds__(256) void attn_kernel(float* __restrict__ attn_out)
{
    extern __shared__ float sm[];
    float* Qs = sm;                 // 54*68
    float* Ks = Qs + 54*68;
    float* Vs = Ks + 54*68;
    float* P  = Vs + 54*68;         // 8*144

    const int tid = threadIdx.x;
    const int blk = blockIdx.x;
    const int bh = blk / NG;
    const int g  = blk - bh * NG;
    const int b  = bh >> 3;
    const int h  = bh & 7;

    const int t_start = g * TPB_TOK;
    const int ntok = (LL - t_start < TPB_TOK) ? (LL - t_start) : TPB_TOK;
    const int n_lo = (7*g - 1 < 0) ? 0 : 7*g - 1;
    const int n_hi = (7*g + 6 > NW-1) ? NW-1 : 7*g + 6;
    const int nwin = n_hi - n_lo + 1;
    const int rows = (n_hi - n_lo)*6 + 12;
    const int row0 = n_lo * 6;

    // base of (b, row0, h, 0); row stride 512 floats
    const size_t base = ((size_t)(b*LL + row0)*HH + h) * 64;

    {
        const float* srcs[3] = {g_Qp + base, g_Kp + base, g_Vp + base};
        float* dsts[3] = {Qs, Ks, Vs};
        int nf4 = rows * 16;
        #pragma unroll
        for (int m = 0; m < 3; m++) {
            const float* src = srcs[m];
            float* dst = dsts[m];
            for (int idx = tid; idx < nf4; idx += 256) {
                int row = idx >> 4, c4 = idx & 15;
                float4 val = *reinterpret_cast<const float4*>(src + (size_t)row*512 + c4*4);
                *reinterpret_cast<float4*>(&dst[row*68 + c4*4]) = val;
            }
        }
    }
    __syncthreads();

    // ---- scores
    for (int o = tid; o < nwin*144; o += 256) {
        int w = o / 144;
        int r = o - w*144;
        int qi = r / 12, ki = r - qi*12;
        const float* qr = &Qs[(w*6 + qi)*68];
        const float* kr = &Ks[(w*6 + ki)*68];
        unsigned long long s01 = 0ULL, s23 = 0ULL;
        #pragma unroll
        for (int d = 0; d < 64; d += 4) {
            float4 a = *reinterpret_cast<const float4*>(&qr[d]);
            float4 bb = *reinterpret_cast<const float4*>(&kr[d]);
            s01 = ffma2(pack2(a.x, a.y), pack2(bb.x, bb.y), s01);
            s23 = ffma2(pack2(a.z, a.w), pack2(bb.z, bb.w), s23);
        }
        float x0, x1, x2, x3;
        unpack2(s01, x0, x1); unpack2(s23, x2, x3);
        P[o] = (x0 + x1 + x2 + x3) * 0.125f;
    }
    __syncthreads();

    // ---- softmax
    for (int t = tid; t < nwin*12; t += 256) {
        int w = t / 12, qi = t - w*12;
        float* row = &P[w*144 + qi*12];
        float mx = row[0];
        #pragma unroll
        for (int k2 = 1; k2 < 12; k2++) mx = fmaxf(mx, row[k2]);
        float sum = 0.f;
        float e[12];
        #pragma unroll
        for (int k2 = 0; k2 < 12; k2++) { e[k2] = __expf(row[k2] - mx); sum += e[k2]; }
        float inv = 1.f / sum;
        #pragma unroll
        for (int k2 = 0; k2 < 12; k2++) row[k2] = e[k2] * inv;
    }
    __syncthreads();

    // ---- write attention probabilities for windows [7g, min(7g+7, NW))
    if (attn_out) {
        int wn0 = 7*g;
        int wn1 = (7*g + 7 < NW) ? 7*g + 7 : NW;
        int nw_out = wn1 - wn0;
        float* dst = attn_out + ((size_t)bh*NW + wn0)*144;
        const float* src = P + (wn0 - n_lo)*144;
        for (int o = tid; o < nw_out*144; o += 256) dst[o] = src[o];
    }

    // ---- finalize tokens: avg of (up to) 2 window contributions
    for (int item = tid; item < ntok*16; item += 256) {
        int t  = t_start + (item >> 4);
        int e4 = (item & 15) * 4;
        int n1 = t / 6;

        unsigned long long a01 = 0ULL, a23 = 0ULL;
        float cnt = 0.f;
        if (n1 <= n_hi) {                       // window n1 valid (n1 <= NW-1)
            int wi = n1 - n_lo;
            int qq = t - n1*6;
            const float* prow = &P[wi*144 + qq*12];
            const float* vb = &Vs[(wi*6)*68 + e4];
            #pragma unroll
            for (int k2 = 0; k2 < 12; k2++) {
                float4 vv = *reinterpret_cast<const float4*>(&vb[k2*68]);
                unsigned long long pk = pack2(prow[k2], prow[k2]);
                a01 = ffma2(pk, pack2(vv.x, vv.y), a01);
                a23 = ffma2(pk, pack2(vv.z, vv.w), a23);
            }
            cnt += 1.f;
        }
        if (n1 >= 1 && n1 - 1 >= n_lo) {        // window n1-1
            int wi = n1 - 1 - n_lo;
            int qq = t - (n1-1)*6;              // in [6,12)
            const float* prow = &P[wi*144 + qq*12];
            const float* vb = &Vs[(wi*6)*68 + e4];
            #pragma unroll
            for (int k2 = 0; k2 < 12; k2++) {
                float4 vv = *reinterpret_cast<const float4*>(&vb[k2*68]);
                unsigned long long pk = pack2(prow[k2], prow[k2]);
                a01 = ffma2(pk, pack2(vv.x, vv.y), a01);
                a23 = ffma2(pk, pack2(vv.z, vv.w), a23);
            }
            cnt += 1.f;
        }
        float inv = 1.f / cnt;
        float o0, o1, o2, o3;
        unpack2(a01, o0, o1); unpack2(a23, o2, o3);
        *reinterpret_cast<float4*>(
            &g_att[((size_t)(b*LL + t)*HH + h)*64 + e4]) =
            make_float4(o0*inv, o1*inv, o2*inv, o3*inv);
    }
}

// =============================================================================
// Kernel 3: residual + LayerNorm over dense g_att [B,L,512]
// =============================================================================
__global__ __launch_bounds__(128) void combine_kernel(
    const float* __restrict__ queries, const float* __restrict__ gamma,
    const float* __restrict__ beta, float* __restrict__ z)
{
    __shared__ float red[8];

    const int tid = threadIdx.x;
    const int tok = blockIdx.x;
    const int c0 = tid * 4;

    float4 a = *reinterpret_cast<const float4*>(&g_att[(size_t)tok*DM + c0]);
    float4 resid = *reinterpret_cast<const float4*>(&queries[(size_t)tok*DM + c0]);
    float4 x;
    x.x = a.x + resid.x; x.y = a.y + resid.y;
    x.z = a.z + resid.z; x.w = a.w + resid.w;

    float s  = x.x + x.y + x.z + x.w;
    float ss = x.x*x.x + x.y*x.y + x.z*x.z + x.w*x.w;
    #pragma unroll
    for (int off = 16; off > 0; off >>= 1) {
        s  += __shfl_down_sync(0xFFFFFFFFu, s, off);
        ss += __shfl_down_sync(0xFFFFFFFFu, ss, off);
    }
    int wid = tid >> 5, lane = tid & 31;
    if (lane == 0) { red[wid] = s; red[4 + wid] = ss; }
    __syncthreads();
    float ts  = red[0] + red[1] + red[2] + red[3];
    float tss = red[4] + red[5] + red[6] + red[7];
    float mean = ts * (1.f / DM);
    float var  = tss * (1.f / DM) - mean*mean;
    float rstd = rsqrtf(var + LNEPS);

    float4 gg = *reinterpret_cast<const float4*>(&gamma[c0]);
    float4 bta = *reinterpret_cast<const float4*>(&beta[c0]);
    float4 o;
    o.x = (x.x - mean)*rstd*gg.x + bta.x;
    o.y = (x.y - mean)*rstd*gg.y + bta.y;
    o.z = (x.z - mean)*rstd*gg.z + bta.z;
    o.w = (x.w - mean)*rstd*gg.w + bta.w;
    *reinterpret_cast<float4*>(&z[(size_t)tok*DM + c0]) = o;
}

// =============================================================================
extern "C" void kernel_launch(void* const* d_in, const int* in_sizes, int n_in,
                              void* d_out, int out_size) {
    const float* queries = (const float*)d_in[0];
    const float* keys    = (const float*)d_in[1];
    const float* values  = (const float*)d_in[2];
    const float* Wq      = (const float*)d_in[3];
    const float* Wk      = (const float*)d_in[4];
    const float* Wv      = (const float*)d_in[5];
    const float* gamma   = (const float*)d_in[6];
    const float* beta    = (const float*)d_in[7];

    float* z = (float*)d_out;
    const long Z = (long)BB * LL * DM;
    const long A = (long)BB * HH * NW * WS * WS;
    float* attn_out = nullptr;
    if ((long)out_size >= Z + A) attn_out = z + Z;

    const int proj_smem = PROJ_SMEM_BF16 * 2;               // 55296 B
    const int attn_smem = (3*54*68 + 8*144) * 4;            // 48672 B
    static bool attr_set = false;
    if (!attr_set) {
        cudaFuncSetAttribute(proj_kernel, cudaFuncAttributeMaxDynamicSharedMemorySize, proj_smem);
        cudaFuncSetAttribute(attn_kernel, cudaFuncAttributeMaxDynamicSharedMemorySize, attn_smem);
        attr_set = true;
    }

    prep_kernel<<<3, 256>>>(Wq, Wk, Wv);
    dim3 pgrid(MROWS/128, 3);
    proj_kernel<<<pgrid, 256, proj_smem>>>(queries, keys, values);
    attn_kernel<<<BB*HH*NG, 256, attn_smem>>>(attn_out);
    combine_kernel<<<BB*LL, 128>>>(queries, gamma, beta, z);
}